// round 1
// baseline (speedup 1.0000x reference)
#include <cuda_runtime.h>
#include <cstdint>

#define D_MODEL 2048
#define NUM_EXPERTS 64
#define M_TILE 128
#define KC 16
#define XS 132   // smem row-stride for x tile (floats), 16B-aligned rows, <=2-way store conflicts
#define WS 68    // smem row-stride for w tile
#define NTHREADS 128
#define LOGIT_STRIDE 66
#define SMEM_FLOATS (M_TILE * LOGIT_STRIDE)  // 8448 > pipeline region (6400)

__device__ __forceinline__ unsigned long long pack2(float lo, float hi) {
    unsigned long long r;
    asm("mov.b64 %0, {%1, %2};" : "=l"(r) : "r"(__float_as_uint(lo)), "r"(__float_as_uint(hi)));
    return r;
}
__device__ __forceinline__ unsigned long long dup2(float v) {
    unsigned long long r;
    unsigned u = __float_as_uint(v);
    asm("mov.b64 %0, {%1, %1};" : "=l"(r) : "r"(u));
    return r;
}
__device__ __forceinline__ void ffma2(unsigned long long& acc, unsigned long long a, unsigned long long b) {
    asm("fma.rn.f32x2 %0, %1, %2, %0;" : "+l"(acc) : "l"(a), "l"(b));
}
__device__ __forceinline__ float2 unpack2(unsigned long long v) {
    unsigned lo, hi;
    asm("mov.b64 {%0, %1}, %2;" : "=r"(lo), "=r"(hi) : "l"(v));
    return make_float2(__uint_as_float(lo), __uint_as_float(hi));
}

__global__ void __launch_bounds__(NTHREADS, 2) router_kernel(
    const float* __restrict__ x,
    const float* __restrict__ w,
    const float* __restrict__ bias,
    float* __restrict__ out,
    int n_rows)
{
    __shared__ float smem[SMEM_FLOATS];
    float* xs0 = smem;
    float* xs1 = smem + KC * XS;
    float* ws0 = smem + 2 * KC * XS;
    float* ws1 = smem + 2 * KC * XS + KC * WS;

    const int tid = threadIdx.x;
    const int tr = tid & 15;   // row-group index 0..15
    const int ec = tid >> 4;   // expert-group index 0..7
    const int lc4 = tid & 3;   // loader: float4-column within KC chunk
    const int lr  = tid >> 2;  // loader: base row/expert (0..31)
    const long long row0 = (long long)blockIdx.x * M_TILE;

    unsigned long long acc[8][4];
#pragma unroll
    for (int i = 0; i < 8; i++)
#pragma unroll
        for (int j = 0; j < 4; j++) acc[i][j] = 0ull;

    float4 xv[4];
    float4 wv[2];

    const float* xbase = x + row0 * D_MODEL;

    auto loadg = [&](int t) {
        const float* xp = xbase + t * KC + lc4 * 4;
#pragma unroll
        for (int l = 0; l < 4; l++) {
            int r = lr + 32 * l;
            xv[l] = *reinterpret_cast<const float4*>(xp + (long long)r * D_MODEL);
        }
        const float* wp = w + t * KC + lc4 * 4;
#pragma unroll
        for (int l = 0; l < 2; l++) {
            int e = lr + 32 * l;
            wv[l] = *reinterpret_cast<const float4*>(wp + (long long)e * D_MODEL);
        }
    };

    auto stores = [&](float* xb, float* wb) {
#pragma unroll
        for (int l = 0; l < 4; l++) {
            int r = lr + 32 * l;
            xb[(lc4 * 4 + 0) * XS + r] = xv[l].x;
            xb[(lc4 * 4 + 1) * XS + r] = xv[l].y;
            xb[(lc4 * 4 + 2) * XS + r] = xv[l].z;
            xb[(lc4 * 4 + 3) * XS + r] = xv[l].w;
        }
#pragma unroll
        for (int l = 0; l < 2; l++) {
            int e = lr + 32 * l;
            wb[(lc4 * 4 + 0) * WS + e] = wv[l].x;
            wb[(lc4 * 4 + 1) * WS + e] = wv[l].y;
            wb[(lc4 * 4 + 2) * WS + e] = wv[l].z;
            wb[(lc4 * 4 + 3) * WS + e] = wv[l].w;
        }
    };

    auto compute = [&](const float* xb, const float* wb) {
#pragma unroll
        for (int k = 0; k < KC; k++) {
            float4 xa  = *reinterpret_cast<const float4*>(xb + k * XS + 4 * tr);
            float4 xb2 = *reinterpret_cast<const float4*>(xb + k * XS + 64 + 4 * tr);
            float4 wa  = *reinterpret_cast<const float4*>(wb + k * WS + 4 * ec);
            float4 wb2 = *reinterpret_cast<const float4*>(wb + k * WS + 32 + 4 * ec);
            unsigned long long wp[4];
            wp[0] = pack2(wa.x, wa.y);
            wp[1] = pack2(wa.z, wa.w);
            wp[2] = pack2(wb2.x, wb2.y);
            wp[3] = pack2(wb2.z, wb2.w);
            float xr8[8] = {xa.x, xa.y, xa.z, xa.w, xb2.x, xb2.y, xb2.z, xb2.w};
#pragma unroll
            for (int i = 0; i < 8; i++) {
                unsigned long long xd = dup2(xr8[i]);
#pragma unroll
                for (int p = 0; p < 4; p++) ffma2(acc[i][p], xd, wp[p]);
            }
        }
    };

    const int T = D_MODEL / KC;  // 128 k-chunks

    loadg(0);
    stores(xs0, ws0);
    __syncthreads();

#pragma unroll 1
    for (int t = 0; t < T - 1; ++t) {
        loadg(t + 1);
        if (t & 1) compute(xs1, ws1);
        else       compute(xs0, ws0);
        if ((t + 1) & 1) stores(xs1, ws1);
        else             stores(xs0, ws0);
        __syncthreads();
    }
    if ((T - 1) & 1) compute(xs1, ws1);
    else             compute(xs0, ws0);

    __syncthreads();  // done reading tiles; smem becomes logits buffer

    // Scatter logits [128][64] (stride 66) to smem
    float* logits = smem;
#pragma unroll
    for (int i = 0; i < 4; i++) {
        int r1 = 4 * tr + i;
        int r2 = 64 + 4 * tr + i;
#pragma unroll
        for (int p = 0; p < 4; p++) {
            float2 v1 = unpack2(acc[i][p]);
            float2 v2 = unpack2(acc[i + 4][p]);
            int e = ((p < 2) ? 0 : 32) + 4 * ec + 2 * (p & 1);
            logits[r1 * LOGIT_STRIDE + e]     = v1.x;
            logits[r1 * LOGIT_STRIDE + e + 1] = v1.y;
            logits[r2 * LOGIT_STRIDE + e]     = v2.x;
            logits[r2 * LOGIT_STRIDE + e + 1] = v2.y;
        }
    }
    __syncthreads();

    // One row per thread: softmax + top-2 + renormalize
    {
        const int r = tid;
        const float* lrow = logits + r * LOGIT_STRIDE;
        float v0 = -3.0e38f, v1 = -3.0e38f;
        int i0 = 0, i1 = 0;
#pragma unroll
        for (int e = 0; e < NUM_EXPERTS; e++) {
            float l = lrow[e] + __ldg(&bias[e]);
            if (l > v0) { v1 = v0; i1 = i0; v0 = l; i0 = e; }
            else if (l > v1) { v1 = l; i1 = e; }
        }
        float Z = 0.0f;
#pragma unroll
        for (int e = 0; e < NUM_EXPERTS; e++) {
            float l = lrow[e] + __ldg(&bias[e]);
            Z += __expf(l - v0);
        }
        float q0 = 1.0f / Z;                 // exp(v0 - v0)/Z
        float q1 = __expf(v1 - v0) / Z;
        float s = q0 + q1 + 1e-8f;
        long long gr = row0 + r;
        out[gr * 2 + 0] = q0 / s;
        out[gr * 2 + 1] = q1 / s;
        float* ido = out + (long long)n_rows * 2;
        ido[gr * 2 + 0] = (float)i0;
        ido[gr * 2 + 1] = (float)i1;
    }
}

extern "C" void kernel_launch(void* const* d_in, const int* in_sizes, int n_in,
                              void* d_out, int out_size) {
    const float* x    = (const float*)d_in[0];
    const float* gw   = (const float*)d_in[1];
    const float* bias = (const float*)d_in[2];
    float* out = (float*)d_out;
    int n_rows = in_sizes[0] / D_MODEL;          // 32768
    int grid = n_rows / M_TILE;                   // 256
    router_kernel<<<grid, NTHREADS>>>(x, gw, bias, out, n_rows);
}